// round 11
// baseline (speedup 1.0000x reference)
#include <cuda_runtime.h>
#include <cuda_fp16.h>
#include <cstdint>
#include <math.h>

#define TOKS 512
#define HDIM 1024
#define FDIM 4096
#define NEXP 8
#define SLOT 512
#define KSPLIT 2
#define RS 40                         // halves per A smem row (80 B, 16B-aligned)
#define SSTF 36                       // floats per B smem row (144 B, 16B-aligned)

// gemm1 smem map (bytes)
#define G1_A   0                      // 3 x (64*80)   = 15360
#define G1_B   15360                  // 3 x (128*144) = 55296 (rows 0-63 w1, 64-127 w3)
#define G1_CTL 70656                  // 3 mbarriers
#define G1_SM  (G1_CTL + 24)
#define G1_AST (64 * 80)              // 5120 B per A stage
#define G1_BST (128 * 144)            // 18432 B per B stage
#define G1_TX  (64 * 64 + 128 * 128)  // 20480 B per stage

// gemm2 smem map
#define G2_A   0                      // 3 x (128*80) = 30720
#define G2_B   30720                  // 3 x (64*144) = 27648
#define G2_CTL 58368
#define G2_SM  (G2_CTL + 24)
#define G2_AST (128 * 80)
#define G2_BST (64 * 144)
#define G2_TX  (128 * 64 + 64 * 128)  // 16384 B per stage

__device__ __half d_xh[TOKS * HDIM];
__device__ __half d_h[NEXP * SLOT * FDIM];
__device__ float  d_po[KSPLIT * NEXP * SLOT * HDIM];
__device__ int    d_count[NEXP];
__device__ int    d_tok[NEXP * SLOT];
__device__ float  d_mult[NEXP * SLOT];
__device__ int    d_pidx[TOKS * 2];

// ---------------- helpers ----------------------------------------------------
__device__ __forceinline__ unsigned pk2(float a, float b) {
    __half2 h = __floats2half2_rn(a, b); return *(unsigned*)&h;
}
__device__ __forceinline__ void mma16(float* c, const unsigned* a, const unsigned* b) {
    asm volatile("mma.sync.aligned.m16n8k16.row.col.f32.f16.f16.f32 "
        "{%0,%1,%2,%3}, {%4,%5,%6,%7}, {%8,%9}, {%0,%1,%2,%3};"
        : "+f"(c[0]), "+f"(c[1]), "+f"(c[2]), "+f"(c[3])
        : "r"(a[0]), "r"(a[1]), "r"(a[2]), "r"(a[3]), "r"(b[0]), "r"(b[1]));
}
__device__ __forceinline__ void ldsm4(unsigned* r, unsigned addr) {
    asm volatile("ldmatrix.sync.aligned.m8n8.x4.shared.b16 {%0,%1,%2,%3}, [%4];"
        : "=r"(r[0]), "=r"(r[1]), "=r"(r[2]), "=r"(r[3]) : "r"(addr));
}
__device__ __forceinline__ void bfrag(const float* rowp, unsigned* br) {
    float2 lo = *(const float2*)rowp; float2 hi = *(const float2*)(rowp + 8);
    br[0] = pk2(lo.x, lo.y); br[1] = pk2(hi.x, hi.y);
}
__device__ __forceinline__ void bulkcp(unsigned dst, const void* src, unsigned bytes, unsigned mbar) {
    asm volatile("cp.async.bulk.shared::cluster.global.mbarrier::complete_tx::bytes "
        "[%0], [%1], %2, [%3];" :: "r"(dst), "l"(src), "r"(bytes), "r"(mbar) : "memory");
}
#define MBAR_INIT(m, c)   asm volatile("mbarrier.init.shared.b64 [%0], %1;" :: "r"(m), "r"(c) : "memory")
#define MBAR_EXPECT(m, b) asm volatile("mbarrier.arrive.expect_tx.shared.b64 _, [%0], %1;" :: "r"(m), "r"(b) : "memory")
#define MBAR_WAIT(m, ph)  asm volatile("{\n\t.reg .pred P1;\n\tWL%=:\n\t" \
    "mbarrier.try_wait.parity.acquire.cta.shared::cta.b64 P1, [%0], %1, 0x989680;\n\t" \
    "@P1 bra.uni WD%=;\n\tbra.uni WL%=;\n\tWD%=:\n\t}" \
    :: "r"((unsigned)(m)), "r"((unsigned)(ph)) : "memory")

// ---------------- small kernels ----------------------------------------------
__global__ void convx_kernel(const float* __restrict__ x) {
    if (blockIdx.x == 0 && threadIdx.x < NEXP) d_count[threadIdx.x] = 0;
    int i = (blockIdx.x * 256 + threadIdx.x) * 4;
    float4 v = *(const float4*)(x + i);
    uint2 o; o.x = pk2(v.x, v.y); o.y = pk2(v.z, v.w);
    *(uint2*)&d_xh[i] = o;
}
__global__ void routing_kernel(const float* __restrict__ x, const float* __restrict__ gw) {
    int t = blockIdx.x, tid = threadIdx.x, w = tid >> 5, lane = tid & 31;
    __shared__ float lg[NEXP];
    const float* xr = x + (size_t)t * HDIM;
    const float* gr = gw + (size_t)w * HDIM;
    float s = 0.f;
    for (int i = lane * 4; i < HDIM; i += 128) {
        float4 a = *(const float4*)(xr + i);
        float4 b = *(const float4*)(gr + i);
        s += a.x * b.x + a.y * b.y + a.z * b.z + a.w * b.w;
    }
    #pragma unroll
    for (int o = 16; o; o >>= 1) s += __shfl_xor_sync(0xFFFFFFFFu, s, o);
    if (lane == 0) lg[w] = s;
    __syncthreads();
    if (tid == 0) {
        float l[NEXP];
        #pragma unroll
        for (int e = 0; e < NEXP; e++) l[e] = lg[e];
        int s1 = 0;
        for (int e = 1; e < NEXP; e++) if (l[e] > l[s1]) s1 = e;
        float m1 = l[s1];
        int s2 = (s1 == 0) ? 1 : 0;
        for (int e = 0; e < NEXP; e++) { if (e == s1) continue; if (l[e] > l[s2]) s2 = e; }
        float m2 = l[s2];
        float mult1, mult2;
        {
            float keep[NEXP]; float mx = -1e30f;
            for (int e = 0; e < NEXP; e++) {
                float f = fmaxf(fabsf(l[e]), m1);
                keep[e] = ((m1 - l[e]) / f > 0.02f) ? -1e30f : l[e];
                mx = fmaxf(mx, keep[e]);
            }
            float sum = 0.f, num = 0.f;
            for (int e = 0; e < NEXP; e++) {
                float p = (keep[e] <= -1e30f) ? 0.f : expf(keep[e] - mx);
                sum += p; if (e == s1) num = p;
            }
            mult1 = num / sum;
        }
        {
            float keep[NEXP]; float mx = -1e30f;
            for (int e = 0; e < NEXP; e++) {
                float f = fmaxf(fabsf(l[e]), m2);
                bool msk = ((m2 - l[e]) / f > 0.02f) || (e == s1);
                keep[e] = msk ? -1e30f : l[e];
                mx = fmaxf(mx, keep[e]);
            }
            float sum = 0.f, num = 0.f;
            for (int e = 0; e < NEXP; e++) {
                float p = (keep[e] <= -1e30f) ? 0.f : expf(keep[e] - mx);
                sum += p; if (e == s2) num = p;
            }
            mult2 = num / sum;
        }
        int p = atomicAdd(&d_count[s1], 1);
        d_tok[s1 * SLOT + p] = t; d_mult[s1 * SLOT + p] = mult1;
        d_pidx[t * 2 + 0] = s1 * SLOT + p;
        p = atomicAdd(&d_count[s2], 1);
        d_tok[s2 * SLOT + p] = t; d_mult[s2 * SLOT + p] = mult2;
        d_pidx[t * 2 + 1] = s2 * SLOT + p;
    }
}

// ---------------- GEMM1: 64x64 fused w1/w3, bulk-copy fills, fp16 mma --------
__global__ __launch_bounds__(256, 2) void gemm1_kernel(const float* __restrict__ w1,
                                                       const float* __restrict__ w3) {
    extern __shared__ char smem[];
    int e = blockIdx.y >> 3, mtile = blockIdx.y & 7;
    int cnt = d_count[e];
    int m0 = mtile * 64;
    if (m0 >= cnt) return;
    int n0 = blockIdx.x * 64;
    unsigned sb = (unsigned)__cvta_generic_to_shared(smem);
    int tid = threadIdx.x;

    if (tid == 0) {
        MBAR_INIT(sb + G1_CTL, 1); MBAR_INIT(sb + G1_CTL + 8, 1); MBAR_INIT(sb + G1_CTL + 16, 1);
    }
    __syncthreads();

    // bulk agent: tid<64 -> A row tid (64B); 64..127 -> w1 row (128B); 128..191 -> w3 row
    const void* bsrc = 0; unsigned bdst = 0, bsz = 0;
    if (tid < 64) {
        int rr = m0 + tid; if (rr >= cnt) rr = cnt - 1;
        bsrc = d_xh + (size_t)d_tok[e * SLOT + rr] * HDIM;
        bdst = sb + G1_A + (unsigned)tid * 80; bsz = 64;
    } else if (tid < 128) {
        bsrc = w1 + ((size_t)e * FDIM + n0 + tid - 64) * HDIM;
        bdst = sb + G1_B + (unsigned)(tid - 64) * 144; bsz = 128;
    } else if (tid < 192) {
        bsrc = w3 + ((size_t)e * FDIM + n0 + tid - 128) * HDIM;
        bdst = sb + G1_B + (unsigned)(tid - 64) * 144; bsz = 128;
    }
    const int NKT = HDIM / 32;  // 32

    // prologue: stages 0,1
    if (tid == 0) { MBAR_EXPECT(sb + G1_CTL, G1_TX); MBAR_EXPECT(sb + G1_CTL + 8, G1_TX); }
    if (tid < 192) {
        unsigned gsz = (bsz == 64) ? 64u : 128u;
        bulkcp(bdst, bsrc, bsz, sb + G1_CTL);
        bulkcp(bdst + (bsz == 64 ? G1_AST : G1_BST), (const char*)bsrc + gsz, bsz, sb + G1_CTL + 8);
    }

    int warp = tid >> 5, lane = tid & 31;
    int wm = warp >> 2, wn = warp & 3;     // 2x4 warps, warp tile 32x16
    int g = lane >> 2, tg = lane & 3;
    int bq = lane & 3, bn = lane >> 2;
    unsigned aoffm[2];
    #pragma unroll
    for (int mi = 0; mi < 2; mi++)
        aoffm[mi] = (unsigned)((wm * 32 + mi * 16 + (lane & 7) + ((lane >> 3) & 1) * 8) * RS
                               + (lane >> 4) * 8) * 2;

    float acc1[2][2][4] = {}, acc3[2][2][4] = {};

    for (int kt = 0; kt < NKT; kt++) {
        MBAR_WAIT(sb + G1_CTL + (kt % 3) * 8, (kt / 3) & 1);
        __syncthreads();
        int kn = kt + 2;
        if (kn < NKT) {
            unsigned mb = sb + G1_CTL + (kn % 3) * 8;
            if (tid == 0) MBAR_EXPECT(mb, G1_TX);
            if (tid < 192) {
                unsigned gstep = (bsz == 64) ? 64u : 128u;
                unsigned stoff = (unsigned)(kn % 3) * ((bsz == 64) ? G1_AST : G1_BST);
                bulkcp(bdst + stoff, (const char*)bsrc + (unsigned)kn * gstep, bsz, mb);
            }
        }

        unsigned sAc = sb + G1_A + (unsigned)(kt % 3) * G1_AST;
        const float* Bc = (const float*)(smem + G1_B + (kt % 3) * G1_BST);

        #pragma unroll
        for (int ks = 0; ks < 2; ks++) {
            unsigned af[2][4];
            ldsm4(af[0], sAc + aoffm[0] + ks * 32);
            ldsm4(af[1], sAc + aoffm[1] + ks * 32);
            int k0 = ks * 16 + 2 * bq;
            #pragma unroll
            for (int ni = 0; ni < 2; ni++) {
                int rowb = (wn * 16 + ni * 8 + bn) * SSTF + k0;
                unsigned br1[2], br3[2];
                bfrag(Bc + rowb, br1);
                bfrag(Bc + rowb + 64 * SSTF, br3);
                #pragma unroll
                for (int mi = 0; mi < 2; mi++) {
                    mma16(acc1[mi][ni], af[mi], br1);
                    mma16(acc3[mi][ni], af[mi], br3);
                }
            }
        }
    }

    // epilogue: silu(s1)*s3 -> d_h fp16
    #pragma unroll
    for (int mi = 0; mi < 2; mi++)
    #pragma unroll
    for (int ni = 0; ni < 2; ni++)
    #pragma unroll
    for (int h = 0; h < 2; h++) {
        int lr = wm * 32 + mi * 16 + g + h * 8;
        if (m0 + lr < cnt) {
            int col = n0 + wn * 16 + ni * 8 + tg * 2;
            float v1a = acc1[mi][ni][h * 2], v1b = acc1[mi][ni][h * 2 + 1];
            float v3a = acc3[mi][ni][h * 2], v3b = acc3[mi][ni][h * 2 + 1];
            float h0 = v1a * v3a / (1.f + __expf(-v1a));
            float h1 = v1b * v3b / (1.f + __expf(-v1b));
            *(unsigned*)&d_h[((size_t)(e * SLOT + m0 + lr)) * FDIM + col] = pk2(h0, h1);
        }
    }
}

// ---------------- GEMM2: 128x64, split-K x2, bulk fills, fp16 mma ------------
__global__ __launch_bounds__(256, 2) void gemm2_kernel(const float* __restrict__ w2) {
    extern __shared__ char smem[];
    int e = blockIdx.y >> 2, mtile = blockIdx.y & 3;
    int cnt = d_count[e];
    int m0 = mtile * 128;
    if (m0 >= cnt) return;
    int n0 = blockIdx.x * 64;
    int kz = blockIdx.z;
    int kbase = kz * (FDIM / KSPLIT);
    unsigned sb = (unsigned)__cvta_generic_to_shared(smem);
    int tid = threadIdx.x;

    if (tid == 0) {
        MBAR_INIT(sb + G2_CTL, 1); MBAR_INIT(sb + G2_CTL + 8, 1); MBAR_INIT(sb + G2_CTL + 16, 1);
    }
    __syncthreads();

    const void* bsrc = 0; unsigned bdst = 0, bsz = 0;
    if (tid < 128) {
        int rr = m0 + tid; if (rr >= cnt) rr = cnt - 1;
        bsrc = d_h + ((size_t)(e * SLOT) + rr) * FDIM + kbase;
        bdst = sb + G2_A + (unsigned)tid * 80; bsz = 64;
    } else if (tid < 192) {
        bsrc = w2 + ((size_t)e * HDIM + n0 + tid - 128) * FDIM + kbase;
        bdst = sb + G2_B + (unsigned)(tid - 128) * 144; bsz = 128;
    }
    const int NKT = (FDIM / KSPLIT) / 32;   // 64

    if (tid == 0) { MBAR_EXPECT(sb + G2_CTL, G2_TX); MBAR_EXPECT(sb + G2_CTL + 8, G2_TX); }
    if (tid < 192) {
        unsigned gsz = (bsz == 64) ? 64u : 128u;
        bulkcp(bdst, bsrc, bsz, sb + G2_CTL);
        bulkcp(bdst + (bsz == 64 ? G2_AST : G2_BST), (const char*)bsrc + gsz, bsz, sb + G2_CTL + 8);
    }

    int warp = tid >> 5, lane = tid & 31;
    int wm = warp >> 1, wn = warp & 1;     // 4x2 warps, warp tile 32x32
    int g = lane >> 2, tg = lane & 3;
    int bq = lane & 3, bn = lane >> 2;
    unsigned aoffm[2];
    #pragma unroll
    for (int mi = 0; mi < 2; mi++)
        aoffm[mi] = (unsigned)((wm * 32 + mi * 16 + (lane & 7) + ((lane >> 3) & 1) * 8) * RS
                               + (lane >> 4) * 8) * 2;

    float acc[2][4][4] = {};

    for (int kt = 0; kt < NKT; kt++) {
        MBAR_WAIT(sb + G2_CTL + (kt % 3) * 8, (kt / 3) & 1);
        __syncthreads();
        int kn = kt + 2;
        if (kn < NKT) {
            unsigned mb = sb + G2_CTL + (kn % 3) * 8;
            if (tid == 0) MBAR_EXPECT(mb, G2_TX);
            if (tid < 192) {
                unsigned gstep = (bsz == 64) ? 64u : 128u;
                unsigned stoff = (unsigned)(kn % 3) * ((bsz == 64) ? G2_AST : G2_BST);
                bulkcp(bdst + stoff, (const char*)bsrc + (unsigned)kn * gstep, bsz, mb);
            }
        }

        unsigned sAc = sb + G2_A + (unsigned)(kt % 3) * G2_AST;
        const float* Bc = (const float*)(smem + G2_B + (kt % 3) * G2_BST);

        #pragma unroll
        for (int ks = 0; ks < 2; ks++) {
            unsigned af[2][4];
            ldsm4(af[0], sAc + aoffm[0] + ks * 32);
            ldsm4(af[1], sAc + aoffm[1] + ks * 32);
            int k0 = ks * 16 + 2 * bq;
            #pragma unroll
            for (int ni = 0; ni < 4; ni++) {
                int rowb = (wn * 32 + ni * 8 + bn) * SSTF + k0;
                unsigned br[2];
                bfrag(Bc + rowb, br);
                #pragma unroll
                for (int mi = 0; mi < 2; mi++) mma16(acc[mi][ni], af[mi], br);
            }
        }
    }

    float* po = d_po + (size_t)kz * (NEXP * SLOT * HDIM);
    #pragma unroll
    for (int mi = 0; mi < 2; mi++)
    #pragma unroll
    for (int ni = 0; ni < 4; ni++)
    #pragma unroll
    for (int h = 0; h < 2; h++) {
        int lr = wm * 32 + mi * 16 + g + h * 8;
        if (m0 + lr < cnt) {
            float mult = d_mult[e * SLOT + m0 + lr];
            int col = n0 + wn * 32 + ni * 8 + tg * 2;
            float2 o;
            o.x = acc[mi][ni][h * 2]     * mult;
            o.y = acc[mi][ni][h * 2 + 1] * mult;
            *(float2*)&po[((size_t)(e * SLOT + m0 + lr)) * HDIM + col] = o;
        }
    }
}

// ---------------- finalize ---------------------------------------------------
__global__ void finalize_kernel(float* __restrict__ out) {
    int t = blockIdx.x, i = threadIdx.x;
    int p0 = d_pidx[t * 2], p1 = d_pidx[t * 2 + 1];
    float4 o = make_float4(0.f, 0.f, 0.f, 0.f);
    #pragma unroll
    for (int kz = 0; kz < KSPLIT; kz++) {
        const float* po = d_po + (size_t)kz * (NEXP * SLOT * HDIM);
        float4 a = ((const float4*)(po + (size_t)p0 * HDIM))[i];
        float4 b = ((const float4*)(po + (size_t)p1 * HDIM))[i];
        o.x += a.x + b.x; o.y += a.y + b.y;
        o.z += a.z + b.z; o.w += a.w + b.w;
    }
    ((float4*)(out + (size_t)t * HDIM))[i] = o;
}

// ---------------- launch ----------------------------------------------------
extern "C" void kernel_launch(void* const* d_in, const int* in_sizes, int n_in,
                              void* d_out, int out_size) {
    const float* x  = (const float*)d_in[0];
    const float* gw = (const float*)d_in[1];
    const float* w1 = (const float*)d_in[2];
    const float* w2 = (const float*)d_in[3];
    const float* w3 = (const float*)d_in[4];
    float* out = (float*)d_out;

    cudaFuncSetAttribute(gemm1_kernel, cudaFuncAttributeMaxDynamicSharedMemorySize, G1_SM);
    cudaFuncSetAttribute(gemm2_kernel, cudaFuncAttributeMaxDynamicSharedMemorySize, G2_SM);

    convx_kernel<<<TOKS * HDIM / 1024, 256>>>(x);
    routing_kernel<<<TOKS, 256>>>(x, gw);
    gemm1_kernel<<<dim3(FDIM / 64, NEXP * 8), 256, G1_SM>>>(w1, w3);
    gemm2_kernel<<<dim3(HDIM / 64, NEXP * 4, KSPLIT), 256, G2_SM>>>(w2);
    finalize_kernel<<<TOKS, 256>>>(out);
}